// round 7
// baseline (speedup 1.0000x reference)
#include <cuda_runtime.h>

#define NN 64
#define SS 60
#define GG 180
#define BATCH 512
#define SEX 10
#define ROWS 4
#define NT 192
#define NACT 5
#define NROLE 7
#define OO 8
#define II 8

// ---- phase-1 shared memory layout (float offsets) ----
#define OFF_WHH 0
#define OFF_WIH 10800
#define OFF_WP  21600
#define OFF_BHH 26400
#define OFF_BIH 26580
#define OFF_BP  26760
#define OFF_HAS 26820
#define OFF_MASK 27076
#define OFF_NEED 27204
#define OFF_H4  27268
#define OFF_S4  27508
#define OFF_RHO 28468
#define OFF_ZI  28708
#define OFF_DZI 28748
#define SMEM_FLOATS 28788
#define SMEM_BYTES (SMEM_FLOATS * 4)

// ---- global scratch ----
__device__ float g_rho_f[(size_t)NN * BATCH * SS];
__device__ float g_rho_b[(size_t)NN * BATCH * SS];
__device__ float g_gi_f[(size_t)NN * BATCH * GG];
__device__ float g_gi_b[(size_t)NN * BATCH * GG];
__device__ float g_alpha_f[(size_t)BATCH * SS];
__device__ float g_alpha_b[(size_t)BATCH * SS];

__device__ __forceinline__ float sigm(float x) {
    return __fdividef(1.f, 1.f + __expf(-x));
}
__device__ __forceinline__ float tanh_f(float x) {
    float e = __expf(2.f * x);
    return 1.f - __fdividef(2.f, e + 1.f);
}
__device__ __forceinline__ void fma2(unsigned long long& d, unsigned long long a,
                                     unsigned long long b) {
    asm("fma.rn.f32x2 %0, %1, %2, %0;" : "+l"(d) : "l"(a), "l"(b));
}
__device__ __forceinline__ unsigned long long splat2(float w) {
    unsigned long long r;
    asm("mov.b64 %0, {%1, %1};" : "=l"(r) : "f"(w));
    return r;
}
__device__ __forceinline__ float lo32(unsigned long long v) {
    return __uint_as_float((unsigned)v);
}
__device__ __forceinline__ float hi32(unsigned long long v) {
    return __uint_as_float((unsigned)(v >> 32));
}

// One blended GRU step in this block's direction.
__device__ __forceinline__ void gru_step(int node, const float* gi_g, bool& hz, int row0)
{
    extern __shared__ float sm[];
    const int t = threadIdx.x;
    if (t < GG) {
        const float* gib = gi_g + ((size_t)node * BATCH + row0) * GG + t;
        float g0 = gib[0];
        float g1 = gib[GG];
        float g2 = gib[2 * GG];
        float g3 = gib[3 * GG];
        unsigned long long a01 = 0ull, a23 = 0ull;
        if (!hz) {
            const float4* wrow = (const float4*)&sm[OFF_WHH + t * SS];
#pragma unroll
            for (int q = 0; q < SS / 4; q++) {
                float4 w4 = wrow[q];
                ulonglong2 h0 = *(const ulonglong2*)&sm[OFF_H4 + (4 * q + 0) * 4];
                ulonglong2 h1 = *(const ulonglong2*)&sm[OFF_H4 + (4 * q + 1) * 4];
                ulonglong2 h2 = *(const ulonglong2*)&sm[OFF_H4 + (4 * q + 2) * 4];
                ulonglong2 h3 = *(const ulonglong2*)&sm[OFF_H4 + (4 * q + 3) * 4];
                unsigned long long wx = splat2(w4.x), wy = splat2(w4.y);
                unsigned long long wz = splat2(w4.z), ww = splat2(w4.w);
                fma2(a01, wx, h0.x); fma2(a23, wx, h0.y);
                fma2(a01, wy, h1.x); fma2(a23, wy, h1.y);
                fma2(a01, wz, h2.x); fma2(a23, wz, h2.y);
                fma2(a01, ww, h3.x); fma2(a23, ww, h3.y);
            }
        }
        float a0 = lo32(a01), a1 = hi32(a01), a2 = lo32(a23), a3 = hi32(a23);
        float bh = sm[OFF_BHH + t];
        if (t < 2 * SS) {
            *(float4*)&sm[OFF_S4 + t * 4] =
                make_float4(a0 + bh + g0, a1 + bh + g1, a2 + bh + g2, a3 + bh + g3);
        } else {
            *(float4*)&sm[OFF_S4 + t * 4] =
                make_float4(a0 + bh, a1 + bh, a2 + bh, a3 + bh);
            *(float4*)&sm[OFF_S4 + (t + SS) * 4] = make_float4(g0, g1, g2, g3);
        }
    }
    __syncthreads();
    for (int idx = t; idx < SS * ROWS; idx += NT) {
        int b = idx & 3;
        float r  = sigm(sm[OFF_S4 + idx]);
        float zg = sigm(sm[OFF_S4 + SS * ROWS + idx]);
        float nv = tanh_f(fmaf(r, sm[OFF_S4 + 2 * SS * ROWS + idx],
                               sm[OFF_S4 + 3 * SS * ROWS + idx]));
        float hold = hz ? 0.f : sm[OFF_H4 + idx];
        float hnew = (1.f - zg) * nv + zg * hold;
        float blend = sm[OFF_HAS + b * NN + node];
        sm[OFF_H4 + idx] = hold + blend * (hnew - hold);
    }
    __syncthreads();
    hz = false;
}

// rho_i = act([h, z_i, dz_i] @ Wp^T + bp) -> smem RHO + global
__device__ __forceinline__ void project(int node, const float* z, const float* dz,
                                        float* rho_g, bool isfwd, bool hz, int row0)
{
    extern __shared__ float sm[];
    const int t = threadIdx.x;
    if (t < 2 * ROWS * SEX) {
        int which = t / 40;          // 0: z, 1: dz
        int loc = t % 40;
        int b = loc / SEX, u = loc % SEX;
        const float* src = which ? dz : z;
        sm[(which ? OFF_DZI : OFF_ZI) + loc] =
            src[((size_t)(row0 + b)) * NN * SEX + (size_t)node * SEX + u];
    }
    __syncthreads();
    for (int idx = t; idx < SS * ROWS; idx += NT) {
        int o = idx >> 2, b = idx & 3;
        float acc = sm[OFF_BP + o];
        const float4* wrow = (const float4*)&sm[OFF_WP + o * 80];
        if (!hz) {
#pragma unroll
            for (int q = 0; q < SS / 4; q++) {
                float4 w4 = wrow[q];
                acc = fmaf(w4.x, sm[OFF_H4 + (4 * q + 0) * 4 + b], acc);
                acc = fmaf(w4.y, sm[OFF_H4 + (4 * q + 1) * 4 + b], acc);
                acc = fmaf(w4.z, sm[OFF_H4 + (4 * q + 2) * 4 + b], acc);
                acc = fmaf(w4.w, sm[OFF_H4 + (4 * q + 3) * 4 + b], acc);
            }
        }
#pragma unroll
        for (int q = 0; q < (2 * SEX) / 4; q++) {
            float4 w4 = wrow[SS / 4 + q];
            int u = 4 * q;
            // cols 60..69 -> z, 70..79 -> dz
            float v0 = (u < SEX)     ? sm[OFF_ZI + b * SEX + u]           : sm[OFF_DZI + b * SEX + u - SEX];
            float v1 = (u + 1 < SEX) ? sm[OFF_ZI + b * SEX + u + 1]       : sm[OFF_DZI + b * SEX + u + 1 - SEX];
            float v2 = (u + 2 < SEX) ? sm[OFF_ZI + b * SEX + u + 2]       : sm[OFF_DZI + b * SEX + u + 2 - SEX];
            float v3 = (u + 3 < SEX) ? sm[OFF_ZI + b * SEX + u + 3]       : sm[OFF_DZI + b * SEX + u + 3 - SEX];
            acc = fmaf(w4.x, v0, acc);
            acc = fmaf(w4.y, v1, acc);
            acc = fmaf(w4.z, v2, acc);
            acc = fmaf(w4.w, v3, acc);
        }
        float v = isfwd ? tanh_f(acc) : acc;
        sm[OFF_RHO + idx] = v;
        rho_g[((size_t)node * BATCH + row0 + b) * SS + o] = v;
    }
    __syncthreads();
}

// gi[node] = rho[node] @ Wih^T + bih
__device__ __forceinline__ void gi_step(int node, float* gi_g, int row0)
{
    extern __shared__ float sm[];
    const int t = threadIdx.x;
    if (t < GG) {
        unsigned long long a01 = splat2(sm[OFF_BIH + t]);
        unsigned long long a23 = a01;
        const float4* wrow = (const float4*)&sm[OFF_WIH + t * SS];
#pragma unroll
        for (int q = 0; q < SS / 4; q++) {
            float4 w4 = wrow[q];
            ulonglong2 r0 = *(const ulonglong2*)&sm[OFF_RHO + (4 * q + 0) * 4];
            ulonglong2 r1 = *(const ulonglong2*)&sm[OFF_RHO + (4 * q + 1) * 4];
            ulonglong2 r2 = *(const ulonglong2*)&sm[OFF_RHO + (4 * q + 2) * 4];
            ulonglong2 r3 = *(const ulonglong2*)&sm[OFF_RHO + (4 * q + 3) * 4];
            unsigned long long wx = splat2(w4.x), wy = splat2(w4.y);
            unsigned long long wz = splat2(w4.z), ww = splat2(w4.w);
            fma2(a01, wx, r0.x); fma2(a23, wx, r0.y);
            fma2(a01, wy, r1.x); fma2(a23, wy, r1.y);
            fma2(a01, wz, r2.x); fma2(a23, wz, r2.y);
            fma2(a01, ww, r3.x); fma2(a23, ww, r3.y);
        }
        float* gb = gi_g + ((size_t)node * BATCH + row0) * GG + t;
        gb[0] = lo32(a01);
        gb[GG] = hi32(a01);
        gb[2 * GG] = lo32(a23);
        gb[3 * GG] = hi32(a23);
    }
    __syncthreads();
}

__global__ void __launch_bounds__(NT, 2)
phase1_kernel(const float* z, const float* dz, const float* has, const int* adj,
              const float* Wih_f, const float* Whh_f, const float* bih_f, const float* bhh_f,
              const float* Wih_b, const float* Whh_b, const float* bih_b, const float* bhh_b,
              const float* Wf, const float* bf, const float* Wb, const float* bb)
{
    extern __shared__ float sm[];
    const int t = threadIdx.x;
    const int row0 = blockIdx.x * ROWS;
    const int dir = blockIdx.y;          // 0 = fwd, 1 = bwd

    const float* Whh = dir ? Whh_b : Whh_f;
    const float* Wih = dir ? Wih_b : Wih_f;
    const float* Wp  = dir ? Wb    : Wf;
    const float* bhh = dir ? bhh_b : bhh_f;
    const float* bih = dir ? bih_b : bih_f;
    const float* bp  = dir ? bb    : bf;
    float* rho_g = dir ? g_rho_b : g_rho_f;
    float* gi_g  = dir ? g_gi_b  : g_gi_f;
    float* alpha_g = dir ? g_alpha_b : g_alpha_f;

    // ---- stage weights (row-major), biases, has, masks ----
    for (int idx = t; idx < GG * SS; idx += NT) {
        sm[OFF_WHH + idx] = Whh[idx];
        sm[OFF_WIH + idx] = Wih[idx];
    }
    for (int idx = t; idx < SS * (SS + 2 * SEX); idx += NT) sm[OFF_WP + idx] = Wp[idx];
    for (int idx = t; idx < GG; idx += NT) {
        sm[OFF_BHH + idx] = bhh[idx];
        sm[OFF_BIH + idx] = bih[idx];
    }
    if (t < SS) sm[OFF_BP + t] = bp[t];
    for (int idx = t; idx < ROWS * NN; idx += NT)
        sm[OFF_HAS + idx] = has[(size_t)(row0 + idx / NN) * NN + (idx % NN)];
    if (t < NN) {
        unsigned long long pm = 0ull, sk = 0ull;
        for (int j = 0; j < NN; j++) {
            if (adj[j * NN + t]) pm |= 1ull << j;   // predecessors of t
            if (adj[t * NN + j]) sk |= 1ull << j;   // successors of t
        }
        ((unsigned long long*)&sm[OFF_MASK])[t] = dir ? sk : pm;
        bool need = dir ? (pm != 0ull || t < II) : (sk != 0ull || t >= NN - OO);
        ((int*)&sm[OFF_NEED])[t] = need ? 1 : 0;
    }
    __syncthreads();

    const unsigned long long* mask = (const unsigned long long*)&sm[OFF_MASK];
    const int* need = (const int*)&sm[OFF_NEED];

    // ---- DAG pass ----
    for (int k = 0; k < NN; k++) {
        const int i = dir ? NN - 1 - k : k;
        bool hz = true;
        unsigned long long m = mask[i];
        while (m) {
            int j;
            if (dir) { j = 63 - __clzll((long long)m); m &= ~(1ull << j); }   // descending
            else     { j = __ffsll((long long)m) - 1;  m &= m - 1; }          // ascending
            gru_step(j, gi_g, hz, row0);
        }
        project(i, z, dz, rho_g, dir == 0, hz, row0);
        if (need[i]) gi_step(i, gi_g, row0);
    }

    // ---- alpha scan ----
    {
        bool hz = true;
        for (int k = 0; k < OO; k++) {
            int an = dir ? (II - 1 - k) : (NN - OO + k);
            gru_step(an, gi_g, hz, row0);
        }
        for (int idx = t; idx < SS * ROWS; idx += NT) {
            int o = idx >> 2, b = idx & 3;
            alpha_g[(size_t)(row0 + b) * SS + o] = sm[OFF_H4 + idx];
        }
    }
}

// ---- phase 2: heads + psi + softmaxes ----
#define P2_AF 0
#define P2_AB 240
#define P2_WU 480
#define P2_HAS 1320
#define P2_OMG 1576
#define P2_PSI 1600
#define P2_FLOATS (1600 + ROWS * NROLE * NN)

__global__ void __launch_bounds__(NT)
phase2_kernel(const float* has, const float* Wa, const float* ba,
              const float* Wc, const float* bc, const float* Wu, const float* bu,
              float* out)
{
    __shared__ float s2[P2_FLOATS];
    const int t = threadIdx.x;
    const int row0 = blockIdx.x * ROWS;

    for (int idx = t; idx < SS * ROWS; idx += NT) {
        int s = idx >> 2, b = idx & 3;
        s2[P2_AF + idx] = g_alpha_f[(size_t)(row0 + b) * SS + s];
        s2[P2_AB + idx] = g_alpha_b[(size_t)(row0 + b) * SS + s];
    }
    for (int idx = t; idx < NROLE * 2 * SS; idx += NT) s2[P2_WU + idx] = Wu[idx];
    for (int idx = t; idx < ROWS * NN; idx += NT)
        s2[P2_HAS + idx] = has[(size_t)(row0 + idx / NN) * NN + (idx % NN)];
    __syncthreads();

    if (t < ROWS * NACT) {
        int b = t / NACT, a = t % NACT;
        float acc = ba[a];
#pragma unroll
        for (int s = 0; s < SS; s++) {
            acc = fmaf(Wa[a * 2 * SS + s],      s2[P2_AF + s * 4 + b], acc);
            acc = fmaf(Wa[a * 2 * SS + SS + s], s2[P2_AB + s * 4 + b], acc);
        }
        s2[P2_OMG + t] = acc;
    } else if (t < ROWS * NACT + ROWS) {
        int b = t - ROWS * NACT;
        float acc = bc[0];
#pragma unroll
        for (int s = 0; s < SS; s++) {
            acc = fmaf(Wc[s],      s2[P2_AF + s * 4 + b], acc);
            acc = fmaf(Wc[SS + s], s2[P2_AB + s * 4 + b], acc);
        }
        out[(size_t)BATCH * NACT + (size_t)BATCH * NROLE * NN + row0 + b] = acc;
    }
    __syncthreads();
    if (t < ROWS) {
        float mx = -1e30f;
        for (int a = 0; a < NACT; a++) mx = fmaxf(mx, s2[P2_OMG + t * NACT + a]);
        float e[NACT], ssum = 0.f;
        for (int a = 0; a < NACT; a++) {
            e[a] = __expf(s2[P2_OMG + t * NACT + a] - mx);
            ssum += e[a];
        }
        float inv = __fdividef(1.f, ssum);
        for (int a = 0; a < NACT; a++) out[(size_t)(row0 + t) * NACT + a] = e[a] * inv;
    }

    // psi: warp-reduced dots
    {
        int warp = t >> 5, lane = t & 31;
        for (int it = warp; it < ROWS * NROLE * NN; it += NT / 32) {
            int n = it % NN;
            int r = (it / NN) % NROLE;
            int b = it / (NROLE * NN);
            const float* rf = g_rho_f + ((size_t)n * BATCH + row0 + b) * SS;
            const float* rb = g_rho_b + ((size_t)n * BATCH + row0 + b) * SS;
            float p = 0.f;
            for (int s = lane; s < SS; s += 32)
                p += rf[s] * s2[P2_WU + r * 2 * SS + s] + rb[s] * s2[P2_WU + r * 2 * SS + SS + s];
#pragma unroll
            for (int o2 = 16; o2; o2 >>= 1) p += __shfl_xor_sync(0xffffffffu, p, o2);
            if (lane == 0) {
                float mval = s2[P2_HAS + b * NN + n];
                float v = p + bu[r];
                v = mval * v - 60.f * (1.f - mval);
                s2[P2_PSI + (b * NROLE + r) * NN + n] = v;
            }
        }
    }
    __syncthreads();
    for (int p0 = t; p0 < ROWS * NROLE; p0 += NT) {
        int b = p0 / NROLE, r = p0 % NROLE;
        float* rowp = &s2[P2_PSI + (b * NROLE + r) * NN];
        float mx = -1e30f;
        for (int n = 0; n < NN; n++) mx = fmaxf(mx, rowp[n]);
        float ssum = 0.f;
        for (int n = 0; n < NN; n++) { float e = __expf(rowp[n] - mx); rowp[n] = e; ssum += e; }
        float inv = __fdividef(1.f, ssum);
        float* op = out + (size_t)BATCH * NACT + (size_t)(row0 + b) * NROLE * NN + (size_t)r * NN;
        for (int n = 0; n < NN; n++) op[n] = rowp[n] * inv;
    }
}

extern "C" void kernel_launch(void* const* d_in, const int* in_sizes, int n_in,
                              void* d_out, int out_size)
{
    cudaFuncSetAttribute(phase1_kernel, cudaFuncAttributeMaxDynamicSharedMemorySize, SMEM_BYTES);
    dim3 grid1(BATCH / ROWS, 2);
    phase1_kernel<<<grid1, NT, SMEM_BYTES>>>(
        (const float*)d_in[0], (const float*)d_in[1], (const float*)d_in[2], (const int*)d_in[3],
        (const float*)d_in[4], (const float*)d_in[5], (const float*)d_in[6], (const float*)d_in[7],
        (const float*)d_in[8], (const float*)d_in[9], (const float*)d_in[10], (const float*)d_in[11],
        (const float*)d_in[12], (const float*)d_in[13], (const float*)d_in[14], (const float*)d_in[15]);
    phase2_kernel<<<BATCH / ROWS, NT>>>(
        (const float*)d_in[2],
        (const float*)d_in[16], (const float*)d_in[17], (const float*)d_in[18], (const float*)d_in[19],
        (const float*)d_in[20], (const float*)d_in[21], (float*)d_out);
}

// round 10
// speedup vs baseline: 1.0118x; 1.0118x over previous
#include <cuda_runtime.h>

#define NN 64
#define SS 60
#define GG 180
#define BATCH 512
#define SEX 10
#define ROWS 4
#define NT 192
#define NACT 5
#define NROLE 7
#define OO 8
#define II 8

// ---- phase-1 shared memory layout (float offsets) ----
#define OFF_WHH 0
#define OFF_WIH 10800
#define OFF_WP  21600
#define OFF_BHH 26400
#define OFF_BIH 26580
#define OFF_BP  26760
#define OFF_HAS 26820
#define OFF_MASK 27076
#define OFF_NEED 27204
#define OFF_WUH 27268
#define OFF_H4  27688
#define OFF_S4  27928
// overlays inside the S4 region (dead between activation and next edge GEMM):
#define OFF_RHO (OFF_S4)
#define OFF_ZI  (OFF_S4 + 760)
#define OFF_DZI (OFF_S4 + 800)
#define SMEM_FLOATS 28888
#define SMEM_BYTES (SMEM_FLOATS * 4)

// ---- global scratch ----
__device__ float g_gi_f[(size_t)NN * BATCH * GG];
__device__ float g_gi_b[(size_t)NN * BATCH * GG];
__device__ float g_alpha_f[(size_t)BATCH * SS];
__device__ float g_alpha_b[(size_t)BATCH * SS];
__device__ float g_psi_f[(size_t)BATCH * NROLE * NN];
__device__ float g_psi_b[(size_t)BATCH * NROLE * NN];

__device__ __forceinline__ float sigm(float x) {
    return __fdividef(1.f, 1.f + __expf(-x));
}
__device__ __forceinline__ float tanh_f(float x) {
    float e = __expf(2.f * x);
    return 1.f - __fdividef(2.f, e + 1.f);
}
__device__ __forceinline__ void fma2(unsigned long long& d, unsigned long long a,
                                     unsigned long long b) {
    asm("fma.rn.f32x2 %0, %1, %2, %0;" : "+l"(d) : "l"(a), "l"(b));
}
__device__ __forceinline__ unsigned long long splat2(float w) {
    unsigned long long r;
    asm("mov.b64 %0, {%1, %1};" : "=l"(r) : "f"(w));
    return r;
}
__device__ __forceinline__ float lo32(unsigned long long v) {
    return __uint_as_float((unsigned)v);
}
__device__ __forceinline__ float hi32(unsigned long long v) {
    return __uint_as_float((unsigned)(v >> 32));
}

// One blended GRU step in this block's direction.
__device__ __forceinline__ void gru_step(int node, const float* gi_g, bool& hz, int row0)
{
    extern __shared__ float sm[];
    const int t = threadIdx.x;
    if (t < GG) {
        const float* gib = gi_g + ((size_t)node * BATCH + row0) * GG + t;
        float g0 = gib[0];
        float g1 = gib[GG];
        float g2 = gib[2 * GG];
        float g3 = gib[3 * GG];
        unsigned long long a01 = 0ull, a23 = 0ull;
        if (!hz) {
            const float4* wrow = (const float4*)&sm[OFF_WHH + t * SS];
#pragma unroll
            for (int q = 0; q < SS / 4; q++) {
                float4 w4 = wrow[q];
                ulonglong2 h0 = *(const ulonglong2*)&sm[OFF_H4 + (4 * q + 0) * 4];
                ulonglong2 h1 = *(const ulonglong2*)&sm[OFF_H4 + (4 * q + 1) * 4];
                ulonglong2 h2 = *(const ulonglong2*)&sm[OFF_H4 + (4 * q + 2) * 4];
                ulonglong2 h3 = *(const ulonglong2*)&sm[OFF_H4 + (4 * q + 3) * 4];
                unsigned long long wx = splat2(w4.x), wy = splat2(w4.y);
                unsigned long long wz = splat2(w4.z), ww = splat2(w4.w);
                fma2(a01, wx, h0.x); fma2(a23, wx, h0.y);
                fma2(a01, wy, h1.x); fma2(a23, wy, h1.y);
                fma2(a01, wz, h2.x); fma2(a23, wz, h2.y);
                fma2(a01, ww, h3.x); fma2(a23, ww, h3.y);
            }
        }
        float a0 = lo32(a01), a1 = hi32(a01), a2 = lo32(a23), a3 = hi32(a23);
        float bh = sm[OFF_BHH + t];
        if (t < 2 * SS) {
            *(float4*)&sm[OFF_S4 + t * 4] =
                make_float4(a0 + bh + g0, a1 + bh + g1, a2 + bh + g2, a3 + bh + g3);
        } else {
            *(float4*)&sm[OFF_S4 + t * 4] =
                make_float4(a0 + bh, a1 + bh, a2 + bh, a3 + bh);
            *(float4*)&sm[OFF_S4 + (t + SS) * 4] = make_float4(g0, g1, g2, g3);
        }
    }
    __syncthreads();
    for (int idx = t; idx < SS * ROWS; idx += NT) {
        int b = idx & 3;
        float r  = sigm(sm[OFF_S4 + idx]);
        float zg = sigm(sm[OFF_S4 + SS * ROWS + idx]);
        float nv = tanh_f(fmaf(r, sm[OFF_S4 + 2 * SS * ROWS + idx],
                               sm[OFF_S4 + 3 * SS * ROWS + idx]));
        float hold = hz ? 0.f : sm[OFF_H4 + idx];
        float hnew = (1.f - zg) * nv + zg * hold;
        float blend = sm[OFF_HAS + b * NN + node];
        sm[OFF_H4 + idx] = hold + blend * (hnew - hold);
    }
    __syncthreads();
    hz = false;
}

// rho_i = act([h, z_i, dz_i] @ Wp^T + bp) -> smem RHO (overlay on S4)
__device__ __forceinline__ void project(int node, const float* z, const float* dz,
                                        bool isfwd, bool hz, int row0)
{
    extern __shared__ float sm[];
    const int t = threadIdx.x;
    if (t < 2 * ROWS * SEX) {
        int which = t / 40;          // 0: z, 1: dz
        int loc = t % 40;
        int b = loc / SEX, u = loc % SEX;
        const float* src = which ? dz : z;
        sm[(which ? OFF_DZI : OFF_ZI) + loc] =
            src[((size_t)(row0 + b)) * NN * SEX + (size_t)node * SEX + u];
    }
    __syncthreads();
    // compute into registers first (RHO overlays S4; ZI/DZI live at S4+760..840,
    // RHO writes land at S4+0..240 — disjoint, so in-loop writes are safe)
    for (int idx = t; idx < SS * ROWS; idx += NT) {
        int o = idx >> 2, b = idx & 3;
        float acc = sm[OFF_BP + o];
        const float4* wrow = (const float4*)&sm[OFF_WP + o * 80];
        if (!hz) {
#pragma unroll
            for (int q = 0; q < SS / 4; q++) {
                float4 w4 = wrow[q];
                acc = fmaf(w4.x, sm[OFF_H4 + (4 * q + 0) * 4 + b], acc);
                acc = fmaf(w4.y, sm[OFF_H4 + (4 * q + 1) * 4 + b], acc);
                acc = fmaf(w4.z, sm[OFF_H4 + (4 * q + 2) * 4 + b], acc);
                acc = fmaf(w4.w, sm[OFF_H4 + (4 * q + 3) * 4 + b], acc);
            }
        }
#pragma unroll
        for (int q = 0; q < (2 * SEX) / 4; q++) {
            float4 w4 = wrow[SS / 4 + q];
            int u = 4 * q;
            float v0 = (u < SEX)     ? sm[OFF_ZI + b * SEX + u]     : sm[OFF_DZI + b * SEX + u - SEX];
            float v1 = (u + 1 < SEX) ? sm[OFF_ZI + b * SEX + u + 1] : sm[OFF_DZI + b * SEX + u + 1 - SEX];
            float v2 = (u + 2 < SEX) ? sm[OFF_ZI + b * SEX + u + 2] : sm[OFF_DZI + b * SEX + u + 2 - SEX];
            float v3 = (u + 3 < SEX) ? sm[OFF_ZI + b * SEX + u + 3] : sm[OFF_DZI + b * SEX + u + 3 - SEX];
            acc = fmaf(w4.x, v0, acc);
            acc = fmaf(w4.y, v1, acc);
            acc = fmaf(w4.z, v2, acc);
            acc = fmaf(w4.w, v3, acc);
        }
        sm[OFF_RHO + idx] = isfwd ? tanh_f(acc) : acc;
    }
    __syncthreads();
}

// psi partial for this node: 28 warp-reduced 60-dim dots from smem RHO.
__device__ __forceinline__ void psi_step(int node, float* psi_g, int row0)
{
    extern __shared__ float sm[];
    const int t = threadIdx.x;
    int warp = t >> 5, lane = t & 31;
    for (int it = warp; it < ROWS * NROLE; it += NT / 32) {
        int b = it / NROLE, r = it % NROLE;
        float p = 0.f;
        for (int s = lane; s < SS; s += 32)
            p += sm[OFF_RHO + s * 4 + b] * sm[OFF_WUH + r * SS + s];
#pragma unroll
        for (int o2 = 16; o2; o2 >>= 1) p += __shfl_xor_sync(0xffffffffu, p, o2);
        if (lane == 0)
            psi_g[((size_t)(row0 + b) * NROLE + r) * NN + node] = p;
    }
}

// gi[node] = rho[node] @ Wih^T + bih
__device__ __forceinline__ void gi_step(int node, float* gi_g, int row0)
{
    extern __shared__ float sm[];
    const int t = threadIdx.x;
    if (t < GG) {
        unsigned long long a01 = splat2(sm[OFF_BIH + t]);
        unsigned long long a23 = a01;
        const float4* wrow = (const float4*)&sm[OFF_WIH + t * SS];
#pragma unroll
        for (int q = 0; q < SS / 4; q++) {
            float4 w4 = wrow[q];
            ulonglong2 r0 = *(const ulonglong2*)&sm[OFF_RHO + (4 * q + 0) * 4];
            ulonglong2 r1 = *(const ulonglong2*)&sm[OFF_RHO + (4 * q + 1) * 4];
            ulonglong2 r2 = *(const ulonglong2*)&sm[OFF_RHO + (4 * q + 2) * 4];
            ulonglong2 r3 = *(const ulonglong2*)&sm[OFF_RHO + (4 * q + 3) * 4];
            unsigned long long wx = splat2(w4.x), wy = splat2(w4.y);
            unsigned long long wz = splat2(w4.z), ww = splat2(w4.w);
            fma2(a01, wx, r0.x); fma2(a23, wx, r0.y);
            fma2(a01, wy, r1.x); fma2(a23, wy, r1.y);
            fma2(a01, wz, r2.x); fma2(a23, wz, r2.y);
            fma2(a01, ww, r3.x); fma2(a23, ww, r3.y);
        }
        float* gb = gi_g + ((size_t)node * BATCH + row0) * GG + t;
        gb[0] = lo32(a01);
        gb[GG] = hi32(a01);
        gb[2 * GG] = lo32(a23);
        gb[3 * GG] = hi32(a23);
    }
    __syncthreads();
}

__global__ void __launch_bounds__(NT, 2)
phase1_kernel(const float* z, const float* dz, const float* has, const int* adj,
              const float* Wih_f, const float* Whh_f, const float* bih_f, const float* bhh_f,
              const float* Wih_b, const float* Whh_b, const float* bih_b, const float* bhh_b,
              const float* Wf, const float* bf, const float* Wb, const float* bb,
              const float* Wu)
{
    extern __shared__ float sm[];
    const int t = threadIdx.x;
    const int row0 = blockIdx.x * ROWS;
    const int dir = blockIdx.y;          // 0 = fwd, 1 = bwd

    const float* Whh = dir ? Whh_b : Whh_f;
    const float* Wih = dir ? Wih_b : Wih_f;
    const float* Wp  = dir ? Wb    : Wf;
    const float* bhh = dir ? bhh_b : bhh_f;
    const float* bih = dir ? bih_b : bih_f;
    const float* bp  = dir ? bb    : bf;
    float* gi_g  = dir ? g_gi_b  : g_gi_f;
    float* alpha_g = dir ? g_alpha_b : g_alpha_f;
    float* psi_g = dir ? g_psi_b : g_psi_f;

    // ---- stage weights (row-major), biases, has, masks ----
    for (int idx = t; idx < GG * SS; idx += NT) {
        sm[OFF_WHH + idx] = Whh[idx];
        sm[OFF_WIH + idx] = Wih[idx];
    }
    for (int idx = t; idx < SS * (SS + 2 * SEX); idx += NT) sm[OFF_WP + idx] = Wp[idx];
    for (int idx = t; idx < GG; idx += NT) {
        sm[OFF_BHH + idx] = bhh[idx];
        sm[OFF_BIH + idx] = bih[idx];
    }
    if (t < SS) sm[OFF_BP + t] = bp[t];
    for (int idx = t; idx < ROWS * NN; idx += NT)
        sm[OFF_HAS + idx] = has[(size_t)(row0 + idx / NN) * NN + (idx % NN)];
    for (int idx = t; idx < NROLE * SS; idx += NT) {
        int r = idx / SS, s = idx % SS;
        sm[OFF_WUH + idx] = Wu[r * 2 * SS + dir * SS + s];
    }
    if (t < NN) {
        unsigned long long pm = 0ull, sk = 0ull;
        for (int j = 0; j < NN; j++) {
            if (adj[j * NN + t]) pm |= 1ull << j;   // predecessors of t
            if (adj[t * NN + j]) sk |= 1ull << j;   // successors of t
        }
        ((unsigned long long*)&sm[OFF_MASK])[t] = dir ? sk : pm;
        bool need = dir ? (pm != 0ull || t < II) : (sk != 0ull || t >= NN - OO);
        ((int*)&sm[OFF_NEED])[t] = need ? 1 : 0;
    }
    __syncthreads();

    const unsigned long long* mask = (const unsigned long long*)&sm[OFF_MASK];
    const int* need = (const int*)&sm[OFF_NEED];

    // ---- DAG pass ----
    for (int k = 0; k < NN; k++) {
        const int i = dir ? NN - 1 - k : k;
        bool hz = true;
        unsigned long long m = mask[i];
        while (m) {
            int j;
            if (dir) { j = 63 - __clzll((long long)m); m &= ~(1ull << j); }   // descending
            else     { j = __ffsll((long long)m) - 1;  m &= m - 1; }          // ascending
            gru_step(j, gi_g, hz, row0);
        }
        project(i, z, dz, dir == 0, hz, row0);
        psi_step(i, psi_g, row0);          // reads RHO only (no smem writes)
        if (need[i]) gi_step(i, gi_g, row0);   // reads RHO; trailing sync
        else __syncthreads();              // protect RHO before next S4 overwrite
    }

    // ---- alpha scan ----
    {
        bool hz = true;
        for (int k = 0; k < OO; k++) {
            int an = dir ? (II - 1 - k) : (NN - OO + k);
            gru_step(an, gi_g, hz, row0);
        }
        for (int idx = t; idx < SS * ROWS; idx += NT) {
            int o = idx >> 2, b = idx & 3;
            alpha_g[(size_t)(row0 + b) * SS + o] = sm[OFF_H4 + idx];
        }
    }
}

// ---- phase 2: heads + psi assembly + softmaxes (tiny) ----
#define P2_AF 0
#define P2_AB 240
#define P2_HAS 480
#define P2_OMG 736
#define P2_PSI 768
#define P2_FLOATS (P2_PSI + ROWS * NROLE * NN)

__global__ void __launch_bounds__(NT)
phase2_kernel(const float* has, const float* Wa, const float* ba,
              const float* Wc, const float* bc, const float* bu,
              float* out)
{
    __shared__ float s2[P2_FLOATS];
    const int t = threadIdx.x;
    const int row0 = blockIdx.x * ROWS;

    for (int idx = t; idx < SS * ROWS; idx += NT) {
        int s = idx >> 2, b = idx & 3;
        s2[P2_AF + idx] = g_alpha_f[(size_t)(row0 + b) * SS + s];
        s2[P2_AB + idx] = g_alpha_b[(size_t)(row0 + b) * SS + s];
    }
    for (int idx = t; idx < ROWS * NN; idx += NT)
        s2[P2_HAS + idx] = has[(size_t)(row0 + idx / NN) * NN + (idx % NN)];
    __syncthreads();

    if (t < ROWS * NACT) {
        int b = t / NACT, a = t % NACT;
        float acc = ba[a];
#pragma unroll
        for (int s = 0; s < SS; s++) {
            acc = fmaf(Wa[a * 2 * SS + s],      s2[P2_AF + s * 4 + b], acc);
            acc = fmaf(Wa[a * 2 * SS + SS + s], s2[P2_AB + s * 4 + b], acc);
        }
        s2[P2_OMG + t] = acc;
    } else if (t < ROWS * NACT + ROWS) {
        int b = t - ROWS * NACT;
        float acc = bc[0];
#pragma unroll
        for (int s = 0; s < SS; s++) {
            acc = fmaf(Wc[s],      s2[P2_AF + s * 4 + b], acc);
            acc = fmaf(Wc[SS + s], s2[P2_AB + s * 4 + b], acc);
        }
        out[(size_t)BATCH * NACT + (size_t)BATCH * NROLE * NN + row0 + b] = acc;
    }

    // psi assembly: pf + pb + bu, mask, stage to smem (coalesced loads)
    for (int idx = t; idx < ROWS * NROLE * NN; idx += NT) {
        int n = idx % NN;
        int r = (idx / NN) % NROLE;
        int b = idx / (NROLE * NN);
        size_t g = ((size_t)(row0 + b) * NROLE + r) * NN + n;
        float v = g_psi_f[g] + g_psi_b[g] + bu[r];
        float m = s2[P2_HAS + b * NN + n];
        s2[P2_PSI + idx] = m * v - 60.f * (1.f - m);
    }
    __syncthreads();

    if (t < ROWS) {
        float mx = -1e30f;
        for (int a = 0; a < NACT; a++) mx = fmaxf(mx, s2[P2_OMG + t * NACT + a]);
        float e[NACT], ssum = 0.f;
        for (int a = 0; a < NACT; a++) {
            e[a] = __expf(s2[P2_OMG + t * NACT + a] - mx);
            ssum += e[a];
        }
        float inv = __fdividef(1.f, ssum);
        for (int a = 0; a < NACT; a++) out[(size_t)(row0 + t) * NACT + a] = e[a] * inv;
    }

    for (int p0 = t; p0 < ROWS * NROLE; p0 += NT) {
        int b = p0 / NROLE, r = p0 % NROLE;
        float* rowp = &s2[P2_PSI + (b * NROLE + r) * NN];
        float mx = -1e30f;
        for (int n = 0; n < NN; n++) mx = fmaxf(mx, rowp[n]);
        float ssum = 0.f;
        for (int n = 0; n < NN; n++) { float e = __expf(rowp[n] - mx); rowp[n] = e; ssum += e; }
        float inv = __fdividef(1.f, ssum);
        float* op = out + (size_t)BATCH * NACT + (size_t)(row0 + b) * NROLE * NN + (size_t)r * NN;
        for (int n = 0; n < NN; n++) op[n] = rowp[n] * inv;
    }
}

extern "C" void kernel_launch(void* const* d_in, const int* in_sizes, int n_in,
                              void* d_out, int out_size)
{
    cudaFuncSetAttribute(phase1_kernel, cudaFuncAttributeMaxDynamicSharedMemorySize, SMEM_BYTES);
    dim3 grid1(BATCH / ROWS, 2);
    phase1_kernel<<<grid1, NT, SMEM_BYTES>>>(
        (const float*)d_in[0], (const float*)d_in[1], (const float*)d_in[2], (const int*)d_in[3],
        (const float*)d_in[4], (const float*)d_in[5], (const float*)d_in[6], (const float*)d_in[7],
        (const float*)d_in[8], (const float*)d_in[9], (const float*)d_in[10], (const float*)d_in[11],
        (const float*)d_in[12], (const float*)d_in[13], (const float*)d_in[14], (const float*)d_in[15],
        (const float*)d_in[20]);
    phase2_kernel<<<BATCH / ROWS, NT>>>(
        (const float*)d_in[2],
        (const float*)d_in[16], (const float*)d_in[17], (const float*)d_in[18], (const float*)d_in[19],
        (const float*)d_in[21], (float*)d_out);
}

// round 12
// speedup vs baseline: 1.0631x; 1.0507x over previous
#include <cuda_runtime.h>

#define NN 64
#define SS 60
#define GG 180
#define BATCH 512
#define SEX 10
#define ROWS 4
#define NT 192
#define NBG (BATCH / ROWS)
#define NACT 5
#define NROLE 7
#define OO 8
#define II 8

// ---- phase-1 shared memory layout (float offsets) ----
#define OFF_W3   0          // whh gate-interleaved [o][s][4] stride 61 float4s: 60*61*4
#define OFF_WIH  14640      // 180*60
#define OFF_BHH3 25440      // [o][4] = {r,z,n,-}
#define OFF_BIH  25680      // 180
#define OFF_BP   25860      // 60
#define OFF_HAS  25920      // [b][64]
#define OFF_MASK 26176      // 64 ull
#define OFF_NEED 26304      // 64 int
#define OFF_WUH  26368      // 7*60
#define OFF_HA   26788      // h ping [s][4]
#define OFF_HB   27028      // h pong [s][4]
#define OFF_RHO  27268      // [s][4]
#define OFF_ZI   27508
#define OFF_DZI  27548
#define SMEM_FLOATS 27588
#define SMEM_BYTES (SMEM_FLOATS * 4)

// ---- global scratch ----
// gi layout: [node][bg][o][gate][4 rows]
__device__ float g_gi_f[(size_t)NN * NBG * SS * 12];
__device__ float g_gi_b[(size_t)NN * NBG * SS * 12];
__device__ float g_alpha_f[(size_t)BATCH * SS];
__device__ float g_alpha_b[(size_t)BATCH * SS];
__device__ float g_psi_f[(size_t)BATCH * NROLE * NN];
__device__ float g_psi_b[(size_t)BATCH * NROLE * NN];

__device__ __forceinline__ float sigm(float x) {
    return __fdividef(1.f, 1.f + __expf(-x));
}
__device__ __forceinline__ float tanh_f(float x) {
    float e = __expf(2.f * x);
    return 1.f - __fdividef(2.f, e + 1.f);
}
__device__ __forceinline__ void fma2(unsigned long long& d, unsigned long long a,
                                     unsigned long long b) {
    asm("fma.rn.f32x2 %0, %1, %2, %0;" : "+l"(d) : "l"(a), "l"(b));
}
__device__ __forceinline__ unsigned long long splat2(float w) {
    unsigned long long r;
    asm("mov.b64 %0, {%1, %1};" : "=l"(r) : "f"(w));
    return r;
}
__device__ __forceinline__ float lo32(unsigned long long v) {
    return __uint_as_float((unsigned)v);
}
__device__ __forceinline__ float hi32(unsigned long long v) {
    return __uint_as_float((unsigned)(v >> 32));
}

// Fused GRU step: GEMM (all 3 gates) + activation + blend + H write, ONE barrier.
// Active lanes: [gw, gw+60). Reads curH, writes nxtH (caller swaps).
__device__ __forceinline__ void gru_fused(int node, const float* gi4, bool& hz,
                                          int bg, int gw, int curH, int nxtH)
{
    extern __shared__ float sm[];
    const int t = threadIdx.x;
    const int o = t - gw;
    if (o >= 0 && o < SS) {
        const float4* gp = (const float4*)(gi4 + (((size_t)node * NBG + bg) * SS + o) * 12);
        float4 gR = gp[0];
        float4 gZ = gp[1];
        float4 gN = gp[2];
        unsigned long long aR01 = 0, aR23 = 0, aZ01 = 0, aZ23 = 0, aN01 = 0, aN23 = 0;
        if (!hz) {
            const float4* wrow = (const float4*)&sm[OFF_W3 + o * 244];
#pragma unroll 10
            for (int s = 0; s < SS; s++) {
                float4 w = wrow[s];
                ulonglong2 h = *(const ulonglong2*)&sm[curH + s * 4];
                unsigned long long ur = splat2(w.x);
                unsigned long long uz = splat2(w.y);
                unsigned long long un = splat2(w.z);
                fma2(aR01, ur, h.x); fma2(aR23, ur, h.y);
                fma2(aZ01, uz, h.x); fma2(aZ23, uz, h.y);
                fma2(aN01, un, h.x); fma2(aN23, un, h.y);
            }
        }
        float4 bh = *(const float4*)&sm[OFF_BHH3 + o * 4];
        float aR[4] = {lo32(aR01), hi32(aR01), lo32(aR23), hi32(aR23)};
        float aZ[4] = {lo32(aZ01), hi32(aZ01), lo32(aZ23), hi32(aZ23)};
        float aN[4] = {lo32(aN01), hi32(aN01), lo32(aN23), hi32(aN23)};
        float gRv[4] = {gR.x, gR.y, gR.z, gR.w};
        float gZv[4] = {gZ.x, gZ.y, gZ.z, gZ.w};
        float gNv[4] = {gN.x, gN.y, gN.z, gN.w};
        float4 hold4 = hz ? make_float4(0.f, 0.f, 0.f, 0.f)
                          : *(const float4*)&sm[curH + o * 4];
        float hold[4] = {hold4.x, hold4.y, hold4.z, hold4.w};
        float res[4];
#pragma unroll
        for (int b = 0; b < 4; b++) {
            float r  = sigm(aR[b] + bh.x + gRv[b]);
            float zg = sigm(aZ[b] + bh.y + gZv[b]);
            float nv = tanh_f(fmaf(r, aN[b] + bh.z, gNv[b]));
            float hnew = (1.f - zg) * nv + zg * hold[b];
            float blend = sm[OFF_HAS + b * NN + node];
            res[b] = hold[b] + blend * (hnew - hold[b]);
        }
        *(float4*)&sm[nxtH + o * 4] = make_float4(res[0], res[1], res[2], res[3]);
    }
    __syncthreads();
    hz = false;
}

// rho_i = act([h, z_i, dz_i] @ Wp^T + bp) -> smem RHO. Wp read from global (L2).
__device__ __forceinline__ void project(int node, const float* z, const float* dz,
                                        const float* Wp, bool isfwd, bool hz,
                                        int row0, int curH)
{
    extern __shared__ float sm[];
    const int t = threadIdx.x;
    if (t < 2 * ROWS * SEX) {
        int which = t / 40;
        int loc = t % 40;
        int b = loc / SEX, u = loc % SEX;
        const float* src = which ? dz : z;
        sm[(which ? OFF_DZI : OFF_ZI) + loc] =
            src[((size_t)(row0 + b)) * NN * SEX + (size_t)node * SEX + u];
    }
    __syncthreads();
    for (int idx = t; idx < SS * ROWS; idx += NT) {
        int o = idx >> 2, b = idx & 3;
        float acc = sm[OFF_BP + o];
        const float4* wrow = (const float4*)(Wp + o * 80);
        if (!hz) {
#pragma unroll
            for (int q = 0; q < SS / 4; q++) {
                float4 w4 = wrow[q];
                acc = fmaf(w4.x, sm[curH + (4 * q + 0) * 4 + b], acc);
                acc = fmaf(w4.y, sm[curH + (4 * q + 1) * 4 + b], acc);
                acc = fmaf(w4.z, sm[curH + (4 * q + 2) * 4 + b], acc);
                acc = fmaf(w4.w, sm[curH + (4 * q + 3) * 4 + b], acc);
            }
        }
#pragma unroll
        for (int q = 0; q < (2 * SEX) / 4; q++) {
            float4 w4 = wrow[SS / 4 + q];
            int u = 4 * q;
            float v0 = (u < SEX)     ? sm[OFF_ZI + b * SEX + u]     : sm[OFF_DZI + b * SEX + u - SEX];
            float v1 = (u + 1 < SEX) ? sm[OFF_ZI + b * SEX + u + 1] : sm[OFF_DZI + b * SEX + u + 1 - SEX];
            float v2 = (u + 2 < SEX) ? sm[OFF_ZI + b * SEX + u + 2] : sm[OFF_DZI + b * SEX + u + 2 - SEX];
            float v3 = (u + 3 < SEX) ? sm[OFF_ZI + b * SEX + u + 3] : sm[OFF_DZI + b * SEX + u + 3 - SEX];
            acc = fmaf(w4.x, v0, acc);
            acc = fmaf(w4.y, v1, acc);
            acc = fmaf(w4.z, v2, acc);
            acc = fmaf(w4.w, v3, acc);
        }
        sm[OFF_RHO + idx] = isfwd ? tanh_f(acc) : acc;
    }
    __syncthreads();
}

// gi (lanes 0..179, optional) + psi (lanes 180..186, always) in ONE step.
__device__ __forceinline__ void gi_psi_step(int node, float* gi4, float* psi_g,
                                            bool doGi, int row0, int bg)
{
    extern __shared__ float sm[];
    const int t = threadIdx.x;
    if (t < GG) {
        if (doGi) {
            unsigned long long a01 = splat2(sm[OFF_BIH + t]);
            unsigned long long a23 = a01;
            const float4* wrow = (const float4*)&sm[OFF_WIH + t * SS];
#pragma unroll
            for (int q = 0; q < SS / 4; q++) {
                float4 w4 = wrow[q];
                ulonglong2 r0 = *(const ulonglong2*)&sm[OFF_RHO + (4 * q + 0) * 4];
                ulonglong2 r1 = *(const ulonglong2*)&sm[OFF_RHO + (4 * q + 1) * 4];
                ulonglong2 r2 = *(const ulonglong2*)&sm[OFF_RHO + (4 * q + 2) * 4];
                ulonglong2 r3 = *(const ulonglong2*)&sm[OFF_RHO + (4 * q + 3) * 4];
                unsigned long long wx = splat2(w4.x), wy = splat2(w4.y);
                unsigned long long wz = splat2(w4.z), ww = splat2(w4.w);
                fma2(a01, wx, r0.x); fma2(a23, wx, r0.y);
                fma2(a01, wy, r1.x); fma2(a23, wy, r1.y);
                fma2(a01, wz, r2.x); fma2(a23, wz, r2.y);
                fma2(a01, ww, r3.x); fma2(a23, ww, r3.y);
            }
            int o = t % SS, g = t / SS;
            float4* dst = (float4*)(gi4 + (((size_t)node * NBG + bg) * SS + o) * 12) + g;
            *dst = make_float4(lo32(a01), hi32(a01), lo32(a23), hi32(a23));
        }
    } else if (t < GG + NROLE) {
        int r = t - GG;
        unsigned long long a01 = 0, a23 = 0;
#pragma unroll 10
        for (int s = 0; s < SS; s++) {
            unsigned long long w = splat2(sm[OFF_WUH + r * SS + s]);
            ulonglong2 rr = *(const ulonglong2*)&sm[OFF_RHO + s * 4];
            fma2(a01, w, rr.x);
            fma2(a23, w, rr.y);
        }
        psi_g[((size_t)(row0 + 0) * NROLE + r) * NN + node] = lo32(a01);
        psi_g[((size_t)(row0 + 1) * NROLE + r) * NN + node] = hi32(a01);
        psi_g[((size_t)(row0 + 2) * NROLE + r) * NN + node] = lo32(a23);
        psi_g[((size_t)(row0 + 3) * NROLE + r) * NN + node] = hi32(a23);
    }
    __syncthreads();
}

__global__ void __launch_bounds__(NT, 2)
phase1_kernel(const float* z, const float* dz, const float* has, const int* adj,
              const float* Wih_f, const float* Whh_f, const float* bih_f, const float* bhh_f,
              const float* Wih_b, const float* Whh_b, const float* bih_b, const float* bhh_b,
              const float* Wf, const float* bf, const float* Wb, const float* bb,
              const float* Wu)
{
    extern __shared__ float sm[];
    const int t = threadIdx.x;
    const int bg = blockIdx.x;
    const int row0 = bg * ROWS;
    const int dir = blockIdx.y;          // 0 = fwd, 1 = bwd
    const int gw = dir << 6;             // GEMM lanes: fwd warps {0,1}, bwd warps {2,3}

    const float* Whh = dir ? Whh_b : Whh_f;
    const float* Wih = dir ? Wih_b : Wih_f;
    const float* Wp  = dir ? Wb    : Wf;
    const float* bhh = dir ? bhh_b : bhh_f;
    const float* bih = dir ? bih_b : bih_f;
    const float* bp  = dir ? bb    : bf;
    float* gi4    = dir ? g_gi_b    : g_gi_f;
    float* alpha_g = dir ? g_alpha_b : g_alpha_f;
    float* psi_g  = dir ? g_psi_b   : g_psi_f;

    // ---- stage: whh gate-interleaved, wih row-major, biases, has, masks, Wu-half ----
    for (int idx = t; idx < 3 * SS * SS; idx += NT) {
        int g = idx / (SS * SS);
        int rem = idx % (SS * SS);
        int o = rem / SS, s = rem % SS;
        sm[OFF_W3 + (o * 61 + s) * 4 + g] = Whh[(g * SS + o) * SS + s];
    }
    for (int idx = t; idx < GG * SS; idx += NT) sm[OFF_WIH + idx] = Wih[idx];
    for (int idx = t; idx < 3 * SS; idx += NT) {
        int g = idx / SS, o = idx % SS;
        sm[OFF_BHH3 + o * 4 + g] = bhh[g * SS + o];
    }
    for (int idx = t; idx < GG; idx += NT) sm[OFF_BIH + idx] = bih[idx];
    if (t < SS) sm[OFF_BP + t] = bp[t];
    for (int idx = t; idx < ROWS * NN; idx += NT)
        sm[OFF_HAS + idx] = has[(size_t)(row0 + idx / NN) * NN + (idx % NN)];
    for (int idx = t; idx < NROLE * SS; idx += NT) {
        int r = idx / SS, s = idx % SS;
        sm[OFF_WUH + idx] = Wu[r * 2 * SS + dir * SS + s];
    }
    if (t < NN) {
        unsigned long long pm = 0ull, sk = 0ull;
        for (int j = 0; j < NN; j++) {
            if (adj[j * NN + t]) pm |= 1ull << j;   // predecessors of t
            if (adj[t * NN + j]) sk |= 1ull << j;   // successors of t
        }
        ((unsigned long long*)&sm[OFF_MASK])[t] = dir ? sk : pm;
        bool need = dir ? (pm != 0ull || t < II) : (sk != 0ull || t >= NN - OO);
        ((int*)&sm[OFF_NEED])[t] = need ? 1 : 0;
    }
    __syncthreads();

    const unsigned long long* mask = (const unsigned long long*)&sm[OFF_MASK];
    const int* need = (const int*)&sm[OFF_NEED];

    int curH = OFF_HA, nxtH = OFF_HB;

    // ---- DAG pass ----
    for (int k = 0; k < NN; k++) {
        const int i = dir ? NN - 1 - k : k;
        bool hz = true;
        unsigned long long m = mask[i];
        while (m) {
            int j;
            if (dir) { j = 63 - __clzll((long long)m); m &= ~(1ull << j); }   // descending
            else     { j = __ffsll((long long)m) - 1;  m &= m - 1; }          // ascending
            gru_fused(j, gi4, hz, bg, gw, curH, nxtH);
            int tmp = curH; curH = nxtH; nxtH = tmp;
        }
        project(i, z, dz, Wp, dir == 0, hz, row0, curH);
        gi_psi_step(i, gi4, psi_g, need[i] != 0, row0, bg);
    }

    // ---- alpha scan ----
    {
        bool hz = true;
        for (int k = 0; k < OO; k++) {
            int an = dir ? (II - 1 - k) : (NN - OO + k);
            gru_fused(an, gi4, hz, bg, gw, curH, nxtH);
            int tmp = curH; curH = nxtH; nxtH = tmp;
        }
        for (int idx = t; idx < SS * ROWS; idx += NT) {
            int o = idx >> 2, b = idx & 3;
            alpha_g[(size_t)(row0 + b) * SS + o] = sm[curH + idx];
        }
    }
}

// ---- phase 2: heads + psi assembly + softmaxes (tiny) ----
#define P2_AF 0
#define P2_AB 240
#define P2_HAS 480
#define P2_OMG 736
#define P2_PSI 768
#define P2_FLOATS (P2_PSI + ROWS * NROLE * NN)

__global__ void __launch_bounds__(NT)
phase2_kernel(const float* has, const float* Wa, const float* ba,
              const float* Wc, const float* bc, const float* bu,
              float* out)
{
    __shared__ float s2[P2_FLOATS];
    const int t = threadIdx.x;
    const int row0 = blockIdx.x * ROWS;

    for (int idx = t; idx < SS * ROWS; idx += NT) {
        int s = idx >> 2, b = idx & 3;
        s2[P2_AF + idx] = g_alpha_f[(size_t)(row0 + b) * SS + s];
        s2[P2_AB + idx] = g_alpha_b[(size_t)(row0 + b) * SS + s];
    }
    for (int idx = t; idx < ROWS * NN; idx += NT)
        s2[P2_HAS + idx] = has[(size_t)(row0 + idx / NN) * NN + (idx % NN)];
    __syncthreads();

    if (t < ROWS * NACT) {
        int b = t / NACT, a = t % NACT;
        float acc = ba[a];
#pragma unroll
        for (int s = 0; s < SS; s++) {
            acc = fmaf(Wa[a * 2 * SS + s],      s2[P2_AF + s * 4 + b], acc);
            acc = fmaf(Wa[a * 2 * SS + SS + s], s2[P2_AB + s * 4 + b], acc);
        }
        s2[P2_OMG + t] = acc;
    } else if (t < ROWS * NACT + ROWS) {
        int b = t - ROWS * NACT;
        float acc = bc[0];
#pragma unroll
        for (int s = 0; s < SS; s++) {
            acc = fmaf(Wc[s],      s2[P2_AF + s * 4 + b], acc);
            acc = fmaf(Wc[SS + s], s2[P2_AB + s * 4 + b], acc);
        }
        out[(size_t)BATCH * NACT + (size_t)BATCH * NROLE * NN + row0 + b] = acc;
    }

    for (int idx = t; idx < ROWS * NROLE * NN; idx += NT) {
        int n = idx % NN;
        int r = (idx / NN) % NROLE;
        int b = idx / (NROLE * NN);
        size_t g = ((size_t)(row0 + b) * NROLE + r) * NN + n;
        float v = g_psi_f[g] + g_psi_b[g] + bu[r];
        float m = s2[P2_HAS + b * NN + n];
        s2[P2_PSI + idx] = m * v - 60.f * (1.f - m);
    }
    __syncthreads();

    if (t < ROWS) {
        float mx = -1e30f;
        for (int a = 0; a < NACT; a++) mx = fmaxf(mx, s2[P2_OMG + t * NACT + a]);
        float e[NACT], ssum = 0.f;
        for (int a = 0; a < NACT; a++) {
            e[a] = __expf(s2[P2_OMG + t * NACT + a] - mx);
            ssum += e[a];
        }
        float inv = __fdividef(1.f, ssum);
        for (int a = 0; a < NACT; a++) out[(size_t)(row0 + t) * NACT + a] = e[a] * inv;
    }

    for (int p0 = t; p0 < ROWS * NROLE; p0 += NT) {
        int b = p0 / NROLE, r = p0 % NROLE;
        float* rowp = &s2[P2_PSI + (b * NROLE + r) * NN];
        float mx = -1e30f;
        for (int n = 0; n < NN; n++) mx = fmaxf(mx, rowp[n]);
        float ssum = 0.f;
        for (int n = 0; n < NN; n++) { float e = __expf(rowp[n] - mx); rowp[n] = e; ssum += e; }
        float inv = __fdividef(1.f, ssum);
        float* op = out + (size_t)BATCH * NACT + (size_t)(row0 + b) * NROLE * NN + (size_t)r * NN;
        for (int n = 0; n < NN; n++) op[n] = rowp[n] * inv;
    }
}

extern "C" void kernel_launch(void* const* d_in, const int* in_sizes, int n_in,
                              void* d_out, int out_size)
{
    cudaFuncSetAttribute(phase1_kernel, cudaFuncAttributeMaxDynamicSharedMemorySize, SMEM_BYTES);
    dim3 grid1(NBG, 2);
    phase1_kernel<<<grid1, NT, SMEM_BYTES>>>(
        (const float*)d_in[0], (const float*)d_in[1], (const float*)d_in[2], (const int*)d_in[3],
        (const float*)d_in[4], (const float*)d_in[5], (const float*)d_in[6], (const float*)d_in[7],
        (const float*)d_in[8], (const float*)d_in[9], (const float*)d_in[10], (const float*)d_in[11],
        (const float*)d_in[12], (const float*)d_in[13], (const float*)d_in[14], (const float*)d_in[15],
        (const float*)d_in[20]);
    phase2_kernel<<<NBG, NT>>>(
        (const float*)d_in[2],
        (const float*)d_in[16], (const float*)d_in[17], (const float*)d_in[18], (const float*)d_in[19],
        (const float*)d_in[21], (float*)d_out);
}

// round 13
// speedup vs baseline: 1.1762x; 1.1064x over previous
#include <cuda_runtime.h>

#define NN 64
#define SS 60
#define GG 180
#define BATCH 512
#define SEX 10
#define ROWS 4
#define NT 256
#define NBG (BATCH / ROWS)
#define NACT 5
#define NROLE 7
#define OO 8
#define II 8

// ---- phase-1 shared memory layout (float offsets) ----
#define OFF_WIH  0          // 180*60
#define OFF_BIH  10800      // 180
#define OFF_BHH  10980      // 180 [g*60+o]
#define OFF_BP   11160      // 60
#define OFF_HAS  11220      // [b][64] = 256
#define OFF_MASK 11476      // 64 ull = 128 floats
#define OFF_NEED 11604      // 64
#define OFF_WUH  11668      // 7*60
#define OFF_HBS0 12088      // H ping  [b][64]
#define OFF_HBS1 12344      // H pong  [b][64]
#define OFF_HSB0 12600      // H ping  [s][4]
#define OFF_HSB1 12840      // H pong  [s][4]
#define OFF_S    13080      // 4 x [b*60+o] = 960  (r, z, nA, nG)
#define OFF_RHO  14040      // [s][4]
#define OFF_ZI   14280
#define OFF_DZI  14320
#define SMEM_FLOATS 14360
#define SMEM_BYTES (SMEM_FLOATS * 4)

// ---- global scratch ----
// gi layout: [node][bg][gate][o][4 rows]
__device__ float g_gi_f[(size_t)NN * NBG * 3 * SS * 4];
__device__ float g_gi_b[(size_t)NN * NBG * 3 * SS * 4];
__device__ float g_alpha_f[(size_t)BATCH * SS];
__device__ float g_alpha_b[(size_t)BATCH * SS];
__device__ float g_psi_f[(size_t)BATCH * NROLE * NN];
__device__ float g_psi_b[(size_t)BATCH * NROLE * NN];

__device__ __forceinline__ float sigm(float x) {
    return __fdividef(1.f, 1.f + __expf(-x));
}
__device__ __forceinline__ float tanh_f(float x) {
    float e = __expf(2.f * x);
    return 1.f - __fdividef(2.f, e + 1.f);
}
__device__ __forceinline__ void fma2(unsigned long long& d, unsigned long long a,
                                     unsigned long long b) {
    asm("fma.rn.f32x2 %0, %1, %2, %0;" : "+l"(d) : "l"(a), "l"(b));
}
__device__ __forceinline__ unsigned long long splat2(float w) {
    unsigned long long r;
    asm("mov.b64 %0, {%1, %1};" : "=l"(r) : "f"(w));
    return r;
}
__device__ __forceinline__ float lo32(unsigned long long v) {
    return __uint_as_float((unsigned)v);
}
__device__ __forceinline__ float hi32(unsigned long long v) {
    return __uint_as_float((unsigned)(v >> 32));
}

// One GRU edge step: gate-split GEMM (6 warps, weights in regs) + exchange + act.
// wp: 30 register w-pairs over s for this lane's (gate g, output o).
__device__ __forceinline__ void gru_step(int node, const float* gi4, bool& hz,
                                         int bg, bool gemmActive, int g, int o,
                                         const unsigned long long* wp,
                                         int curBS, int nxtBS, int nxtSB)
{
    extern __shared__ float sm[];
    const int t = threadIdx.x;
    if (gemmActive) {
        const float4 gi = *(const float4*)(gi4 +
            ((((size_t)node * NBG + bg) * 3 + g) * SS + o) * 4);
        unsigned long long acc0 = 0, acc1 = 0, acc2 = 0, acc3 = 0;
        if (!hz) {
#pragma unroll
            for (int q = 0; q < 15; q++) {
                ulonglong2 h0 = *(const ulonglong2*)&sm[curBS + 0 * 64 + 4 * q];
                ulonglong2 h1 = *(const ulonglong2*)&sm[curBS + 1 * 64 + 4 * q];
                ulonglong2 h2 = *(const ulonglong2*)&sm[curBS + 2 * 64 + 4 * q];
                ulonglong2 h3 = *(const ulonglong2*)&sm[curBS + 3 * 64 + 4 * q];
                fma2(acc0, wp[2 * q], h0.x); fma2(acc0, wp[2 * q + 1], h0.y);
                fma2(acc1, wp[2 * q], h1.x); fma2(acc1, wp[2 * q + 1], h1.y);
                fma2(acc2, wp[2 * q], h2.x); fma2(acc2, wp[2 * q + 1], h2.y);
                fma2(acc3, wp[2 * q], h3.x); fma2(acc3, wp[2 * q + 1], h3.y);
            }
        }
        float bh = sm[OFF_BHH + g * SS + o];
        float a0 = lo32(acc0) + hi32(acc0) + bh;
        float a1 = lo32(acc1) + hi32(acc1) + bh;
        float a2 = lo32(acc2) + hi32(acc2) + bh;
        float a3 = lo32(acc3) + hi32(acc3) + bh;
        if (g < 2) {
            sm[OFF_S + g * 240 + 0 * 60 + o] = a0 + gi.x;
            sm[OFF_S + g * 240 + 1 * 60 + o] = a1 + gi.y;
            sm[OFF_S + g * 240 + 2 * 60 + o] = a2 + gi.z;
            sm[OFF_S + g * 240 + 3 * 60 + o] = a3 + gi.w;
        } else {
            sm[OFF_S + 2 * 240 + 0 * 60 + o] = a0;
            sm[OFF_S + 2 * 240 + 1 * 60 + o] = a1;
            sm[OFF_S + 2 * 240 + 2 * 60 + o] = a2;
            sm[OFF_S + 2 * 240 + 3 * 60 + o] = a3;
            sm[OFF_S + 3 * 240 + 0 * 60 + o] = gi.x;
            sm[OFF_S + 3 * 240 + 1 * 60 + o] = gi.y;
            sm[OFF_S + 3 * 240 + 2 * 60 + o] = gi.z;
            sm[OFF_S + 3 * 240 + 3 * 60 + o] = gi.w;
        }
    }
    __syncthreads();
    if (t < 240) {
        int b = t / 60, o2 = t % 60;
        float r  = sigm(sm[OFF_S + 0 * 240 + t]);
        float zg = sigm(sm[OFF_S + 1 * 240 + t]);
        float nv = tanh_f(fmaf(r, sm[OFF_S + 2 * 240 + t], sm[OFF_S + 3 * 240 + t]));
        float hold = hz ? 0.f : sm[curBS + b * 64 + o2];
        float hnew = (1.f - zg) * nv + zg * hold;
        float blend = sm[OFF_HAS + b * 64 + node];
        float res = hold + blend * (hnew - hold);
        sm[nxtBS + b * 64 + o2] = res;
        sm[nxtSB + o2 * 4 + b] = res;
    }
    __syncthreads();
    hz = false;
}

// rho_i = act([h, z_i, dz_i] @ Wp^T + bp) -> smem RHO [s][4]. Wp from global.
__device__ __forceinline__ void project(int node, const float* z, const float* dz,
                                        const float* Wp, bool isfwd, bool hz,
                                        int row0, int curSB)
{
    extern __shared__ float sm[];
    const int t = threadIdx.x;
    if (t < 2 * ROWS * SEX) {
        int which = t / 40;
        int loc = t % 40;
        int b = loc / SEX, u = loc % SEX;
        const float* src = which ? dz : z;
        sm[(which ? OFF_DZI : OFF_ZI) + loc] =
            src[((size_t)(row0 + b)) * NN * SEX + (size_t)node * SEX + u];
    }
    __syncthreads();
    if (t < SS * ROWS) {
        int o = t >> 2, b = t & 3;
        float acc = sm[OFF_BP + o];
        const float4* wrow = (const float4*)(Wp + o * 80);
        if (!hz) {
#pragma unroll
            for (int q = 0; q < SS / 4; q++) {
                float4 w4 = wrow[q];
                acc = fmaf(w4.x, sm[curSB + (4 * q + 0) * 4 + b], acc);
                acc = fmaf(w4.y, sm[curSB + (4 * q + 1) * 4 + b], acc);
                acc = fmaf(w4.z, sm[curSB + (4 * q + 2) * 4 + b], acc);
                acc = fmaf(w4.w, sm[curSB + (4 * q + 3) * 4 + b], acc);
            }
        }
#pragma unroll
        for (int q = 0; q < (2 * SEX) / 4; q++) {
            float4 w4 = wrow[SS / 4 + q];
            int u = 4 * q;
            float v0 = (u < SEX)     ? sm[OFF_ZI + b * SEX + u]     : sm[OFF_DZI + b * SEX + u - SEX];
            float v1 = (u + 1 < SEX) ? sm[OFF_ZI + b * SEX + u + 1] : sm[OFF_DZI + b * SEX + u + 1 - SEX];
            float v2 = (u + 2 < SEX) ? sm[OFF_ZI + b * SEX + u + 2] : sm[OFF_DZI + b * SEX + u + 2 - SEX];
            float v3 = (u + 3 < SEX) ? sm[OFF_ZI + b * SEX + u + 3] : sm[OFF_DZI + b * SEX + u + 3 - SEX];
            acc = fmaf(w4.x, v0, acc);
            acc = fmaf(w4.y, v1, acc);
            acc = fmaf(w4.z, v2, acc);
            acc = fmaf(w4.w, v3, acc);
        }
        sm[OFF_RHO + t] = isfwd ? tanh_f(acc) : acc;
    }
    __syncthreads();
}

// gi (lanes 0..179, optional, new gate-major layout) + psi (lanes 180..186).
__device__ __forceinline__ void gi_psi_step(int node, float* gi4, float* psi_g,
                                            bool doGi, int row0, int bg)
{
    extern __shared__ float sm[];
    const int t = threadIdx.x;
    if (t < GG) {
        if (doGi) {
            unsigned long long a01 = splat2(sm[OFF_BIH + t]);
            unsigned long long a23 = a01;
            const float4* wrow = (const float4*)&sm[OFF_WIH + t * SS];
#pragma unroll
            for (int q = 0; q < SS / 4; q++) {
                float4 w4 = wrow[q];
                ulonglong2 r0 = *(const ulonglong2*)&sm[OFF_RHO + (4 * q + 0) * 4];
                ulonglong2 r1 = *(const ulonglong2*)&sm[OFF_RHO + (4 * q + 1) * 4];
                ulonglong2 r2 = *(const ulonglong2*)&sm[OFF_RHO + (4 * q + 2) * 4];
                ulonglong2 r3 = *(const ulonglong2*)&sm[OFF_RHO + (4 * q + 3) * 4];
                unsigned long long wx = splat2(w4.x), wy = splat2(w4.y);
                unsigned long long wz = splat2(w4.z), ww = splat2(w4.w);
                fma2(a01, wx, r0.x); fma2(a23, wx, r0.y);
                fma2(a01, wy, r1.x); fma2(a23, wy, r1.y);
                fma2(a01, wz, r2.x); fma2(a23, wz, r2.y);
                fma2(a01, ww, r3.x); fma2(a23, ww, r3.y);
            }
            int g = t / SS, o = t % SS;
            float4* dst = (float4*)(gi4 + ((((size_t)node * NBG + bg) * 3 + g) * SS + o) * 4);
            *dst = make_float4(lo32(a01), hi32(a01), lo32(a23), hi32(a23));
        }
    } else if (t < GG + NROLE) {
        int r = t - GG;
        unsigned long long a01 = 0, a23 = 0;
#pragma unroll 10
        for (int s = 0; s < SS; s++) {
            unsigned long long w = splat2(sm[OFF_WUH + r * SS + s]);
            ulonglong2 rr = *(const ulonglong2*)&sm[OFF_RHO + s * 4];
            fma2(a01, w, rr.x);
            fma2(a23, w, rr.y);
        }
        psi_g[((size_t)(row0 + 0) * NROLE + r) * NN + node] = lo32(a01);
        psi_g[((size_t)(row0 + 1) * NROLE + r) * NN + node] = hi32(a01);
        psi_g[((size_t)(row0 + 2) * NROLE + r) * NN + node] = lo32(a23);
        psi_g[((size_t)(row0 + 3) * NROLE + r) * NN + node] = hi32(a23);
    }
    __syncthreads();
}

__global__ void __launch_bounds__(NT, 2)
phase1_kernel(const float* z, const float* dz, const float* has, const int* adj,
              const float* Wih_f, const float* Whh_f, const float* bih_f, const float* bhh_f,
              const float* Wih_b, const float* Whh_b, const float* bih_b, const float* bhh_b,
              const float* Wf, const float* bf, const float* Wb, const float* bb,
              const float* Wu)
{
    extern __shared__ float sm[];
    const int t = threadIdx.x;
    const int warp = t >> 5, lane = t & 31;
    const int bg = blockIdx.x;
    const int row0 = bg * ROWS;
    const int dir = blockIdx.y;

    const float* Whh = dir ? Whh_b : Whh_f;
    const float* Wih = dir ? Wih_b : Wih_f;
    const float* Wp  = dir ? Wb    : Wf;
    const float* bhh = dir ? bhh_b : bhh_f;
    const float* bih = dir ? bih_b : bih_f;
    const float* bp  = dir ? bb    : bf;
    float* gi4     = dir ? g_gi_b    : g_gi_f;
    float* alpha_g = dir ? g_alpha_b : g_alpha_f;
    float* psi_g   = dir ? g_psi_b   : g_psi_f;

    // GEMM warp role: balanced SMSP usage across co-resident fwd/bwd CTAs.
    int role;
    {
        const int tbl0[8] = {0, 1, 2, 3, 4, -1, -1, 5};
        const int tbl1[8] = {0, 1, 2, 3, -1, 4, 5, -1};
        role = dir ? tbl1[warp] : tbl0[warp];
    }
    const int g = (role >= 0) ? role % 3 : 0;
    const int o = (role >= 0) ? (role / 3) * 32 + lane : 0;
    const bool gemmActive = (role >= 0) && (o < SS);

    // Whh row for this lane in registers (30 x f32x2 pairs over s).
    unsigned long long wp[30];
    if (gemmActive) {
        const float* wsrc = Whh + ((size_t)g * SS + o) * SS;
#pragma unroll
        for (int q = 0; q < 30; q++)
            wp[q] = *(const unsigned long long*)(wsrc + 2 * q);
    }

    // ---- stage smem ----
    for (int idx = t; idx < GG * SS; idx += NT) sm[OFF_WIH + idx] = Wih[idx];
    for (int idx = t; idx < GG; idx += NT) {
        sm[OFF_BIH + idx] = bih[idx];
        sm[OFF_BHH + idx] = bhh[idx];
    }
    if (t < SS) sm[OFF_BP + t] = bp[t];
    for (int idx = t; idx < ROWS * NN; idx += NT)
        sm[OFF_HAS + idx] = has[(size_t)(row0 + idx / NN) * NN + (idx % NN)];
    for (int idx = t; idx < NROLE * SS; idx += NT) {
        int r = idx / SS, s = idx % SS;
        sm[OFF_WUH + idx] = Wu[r * 2 * SS + dir * SS + s];
    }
    if (t < NN) {
        unsigned long long pm = 0ull, sk = 0ull;
        for (int j = 0; j < NN; j++) {
            if (adj[j * NN + t]) pm |= 1ull << j;   // predecessors of t
            if (adj[t * NN + j]) sk |= 1ull << j;   // successors of t
        }
        ((unsigned long long*)&sm[OFF_MASK])[t] = dir ? sk : pm;
        bool need = dir ? (pm != 0ull || t < II) : (sk != 0ull || t >= NN - OO);
        ((int*)&sm[OFF_NEED])[t] = need ? 1 : 0;
    }
    __syncthreads();

    const unsigned long long* mask = (const unsigned long long*)&sm[OFF_MASK];
    const int* need = (const int*)&sm[OFF_NEED];

    int curBS = OFF_HBS0, nxtBS = OFF_HBS1;
    int curSB = OFF_HSB0, nxtSB = OFF_HSB1;

    // ---- DAG pass ----
    for (int k = 0; k < NN; k++) {
        const int i = dir ? NN - 1 - k : k;
        bool hz = true;
        unsigned long long m = mask[i];
        while (m) {
            int j;
            if (dir) { j = 63 - __clzll((long long)m); m &= ~(1ull << j); }
            else     { j = __ffsll((long long)m) - 1;  m &= m - 1; }
            gru_step(j, gi4, hz, bg, gemmActive, g, o, wp, curBS, nxtBS, nxtSB);
            int tb = curBS; curBS = nxtBS; nxtBS = tb;
            int ts = curSB; curSB = nxtSB; nxtSB = ts;
        }
        project(i, z, dz, Wp, dir == 0, hz, row0, curSB);
        gi_psi_step(i, gi4, psi_g, need[i] != 0, row0, bg);
    }

    // ---- alpha scan ----
    {
        bool hz = true;
        for (int k = 0; k < OO; k++) {
            int an = dir ? (II - 1 - k) : (NN - OO + k);
            gru_step(an, gi4, hz, bg, gemmActive, g, o, wp, curBS, nxtBS, nxtSB);
            int tb = curBS; curBS = nxtBS; nxtBS = tb;
            int ts = curSB; curSB = nxtSB; nxtSB = ts;
        }
        if (t < SS * ROWS) {
            int o2 = t >> 2, b = t & 3;
            alpha_g[(size_t)(row0 + b) * SS + o2] = sm[curSB + t];
        }
    }
}

// ---- phase 2: heads + psi assembly + softmaxes (tiny) ----
#define P2NT 192
#define P2_AF 0
#define P2_AB 240
#define P2_HAS 480
#define P2_OMG 736
#define P2_PSI 768
#define P2_FLOATS (P2_PSI + ROWS * NROLE * NN)

__global__ void __launch_bounds__(P2NT)
phase2_kernel(const float* has, const float* Wa, const float* ba,
              const float* Wc, const float* bc, const float* bu,
              float* out)
{
    __shared__ float s2[P2_FLOATS];
    const int t = threadIdx.x;
    const int row0 = blockIdx.x * ROWS;

    for (int idx = t; idx < SS * ROWS; idx += P2NT) {
        int s = idx >> 2, b = idx & 3;
        s2[P2_AF + idx] = g_alpha_f[(size_t)(row0 + b) * SS + s];
        s2[P2_AB + idx] = g_alpha_b[(size_t)(row0 + b) * SS + s];
    }
    for (int idx = t; idx < ROWS * NN; idx += P2NT)
        s2[P2_HAS + idx] = has[(size_t)(row0 + idx / NN) * NN + (idx % NN)];
    __syncthreads();

    if (t < ROWS * NACT) {
        int b = t / NACT, a = t % NACT;
        float acc = ba[a];
#pragma unroll
        for (int s = 0; s < SS; s++) {
            acc = fmaf(Wa[a * 2 * SS + s],      s2[P2_AF + s * 4 + b], acc);
            acc = fmaf(Wa[a * 2 * SS + SS + s], s2[P2_AB + s * 4 + b], acc);
        }
        s2[P2_OMG + t] = acc;
    } else if (t < ROWS * NACT + ROWS) {
        int b = t - ROWS * NACT;
        float acc = bc[0];
#pragma unroll
        for (int s = 0; s < SS; s++) {
            acc = fmaf(Wc[s],      s2[P2_AF + s * 4 + b], acc);
            acc = fmaf(Wc[SS + s], s2[P2_AB + s * 4 + b], acc);
        }
        out[(size_t)BATCH * NACT + (size_t)BATCH * NROLE * NN + row0 + b] = acc;
    }

    for (int idx = t; idx < ROWS * NROLE * NN; idx += P2NT) {
        int n = idx % NN;
        int r = (idx / NN) % NROLE;
        int b = idx / (NROLE * NN);
        size_t gg = ((size_t)(row0 + b) * NROLE + r) * NN + n;
        float v = g_psi_f[gg] + g_psi_b[gg] + bu[r];
        float m = s2[P2_HAS + b * NN + n];
        s2[P2_PSI + idx] = m * v - 60.f * (1.f - m);
    }
    __syncthreads();

    if (t < ROWS) {
        float mx = -1e30f;
        for (int a = 0; a < NACT; a++) mx = fmaxf(mx, s2[P2_OMG + t * NACT + a]);
        float e[NACT], ssum = 0.f;
        for (int a = 0; a < NACT; a++) {
            e[a] = __expf(s2[P2_OMG + t * NACT + a] - mx);
            ssum += e[a];
        }
        float inv = __fdividef(1.f, ssum);
        for (int a = 0; a < NACT; a++) out[(size_t)(row0 + t) * NACT + a] = e[a] * inv;
    }

    for (int p0 = t; p0 < ROWS * NROLE; p0 += P2NT) {
        int b = p0 / NROLE, r = p0 % NROLE;
        float* rowp = &s2[P2_PSI + (b * NROLE + r) * NN];
        float mx = -1e30f;
        for (int n = 0; n < NN; n++) mx = fmaxf(mx, rowp[n]);
        float ssum = 0.f;
        for (int n = 0; n < NN; n++) { float e = __expf(rowp[n] - mx); rowp[n] = e; ssum += e; }
        float inv = __fdividef(1.f, ssum);
        float* op = out + (size_t)BATCH * NACT + (size_t)(row0 + b) * NROLE * NN + (size_t)r * NN;
        for (int n = 0; n < NN; n++) op[n] = rowp[n] * inv;
    }
}

extern "C" void kernel_launch(void* const* d_in, const int* in_sizes, int n_in,
                              void* d_out, int out_size)
{
    cudaFuncSetAttribute(phase1_kernel, cudaFuncAttributeMaxDynamicSharedMemorySize, SMEM_BYTES);
    dim3 grid1(NBG, 2);
    phase1_kernel<<<grid1, NT, SMEM_BYTES>>>(
        (const float*)d_in[0], (const float*)d_in[1], (const float*)d_in[2], (const int*)d_in[3],
        (const float*)d_in[4], (const float*)d_in[5], (const float*)d_in[6], (const float*)d_in[7],
        (const float*)d_in[8], (const float*)d_in[9], (const float*)d_in[10], (const float*)d_in[11],
        (const float*)d_in[12], (const float*)d_in[13], (const float*)d_in[14], (const float*)d_in[15],
        (const float*)d_in[20]);
    phase2_kernel<<<NBG, P2NT>>>(
        (const float*)d_in[2],
        (const float*)d_in[16], (const float*)d_in[17], (const float*)d_in[18], (const float*)d_in[19],
        (const float*)d_in[21], (float*)d_out);
}